// round 15
// baseline (speedup 1.0000x reference)
#include <cuda_runtime.h>
#include <cuda_fp16.h>
#include <mma.h>
using namespace nvcuda;

#define NV 20000
#define EE 320000
#define DD 128
#define HD 512
#define LL 3
#define MTILES 157
#define NV2 (MTILES * 128)
#define EPS_ 1.1920929e-07f

// ---------------- static device scratch ----------------
__device__ float  g_x  [NV2 * DD];
__device__ __half g_xh [NV2 * DD];
__device__ __half g_xph[(size_t)NV2 * HD];
__device__ __half g_Wg [LL * DD * HD];
__device__ __half g_W1h[LL * DD * DD];
__device__ __half g_W2h[LL * DD * DD];
__device__ float  g_wsd[LL * 8 * DD];     // folded att weights [L][8][128] (h<4: src, h>=4: dst)
__device__ float  g_as[NV * 4];
__device__ float  g_ad[NV * 4];
__device__ int    g_rowptr[NV + 1];
__device__ int    g_deg[NV];
__device__ int    g_cursor[NV];
__device__ int    g_col[EE + NV];
__device__ int    g_is64;

// ---------------- fused setup ----------------
#define WHALF ((LL * DD * HD + 2 * LL * DD * DD) / 2)

__global__ void k_setup(const float4* __restrict__ x,
                        const float* __restrict__ Wg,
                        const float* __restrict__ W1,
                        const float* __restrict__ W2,
                        const unsigned* __restrict__ ei_w) {
    int i = blockIdx.x * 256 + threadIdx.x;
    if (i < NV * DD / 4) {
        float4 v = x[i];
        ((float4*)g_x)[i] = v;
        ((__half2*)g_xh)[i * 2]     = __floats2half2_rn(v.x, v.y);
        ((__half2*)g_xh)[i * 2 + 1] = __floats2half2_rn(v.z, v.w);
    }
    if (i < WHALF) {
        int j = i * 2;
        const float* src; __half* dst; int off;
        if (j < LL * DD * HD)                     { src = Wg; dst = g_Wg;  off = j; }
        else if (j < LL * DD * HD + LL * DD * DD) { src = W1; dst = g_W1h; off = j - LL * DD * HD; }
        else                                      { src = W2; dst = g_W2h; off = j - LL * DD * HD - LL * DD * DD; }
        float2 v = *(const float2*)(src + off);
        *(__half2*)(dst + off) = __floats2half2_rn(v.x, v.y);
    }
    if (i < NV) g_deg[i] = 1;
    if (blockIdx.x == 0) {
        __shared__ unsigned acc;
        if (threadIdx.x == 0) acc = 0u;
        __syncthreads();
        unsigned v = 0;
        for (int k = threadIdx.x; k < 2048; k += 256) v |= ei_w[2 * k + 1];
        if (v) atomicOr(&acc, 1u);
        __syncthreads();
        if (threadIdx.x == 0) g_is64 = (acc == 0u) ? 1 : 0;
    }
}

// ---------------- fold att vectors through W_gat ----------------
__global__ __launch_bounds__(128) void k_prep(const float* __restrict__ Wg,
                                              const float* __restrict__ att_s,
                                              const float* __restrict__ att_d) {
    int l = blockIdx.x >> 2, h = blockIdx.x & 3;
    int k = threadIdx.x;
    __shared__ float sa[128], sd[128];
    sa[k] = att_s[(l * 4 + h) * 128 + k];
    sd[k] = att_d[(l * 4 + h) * 128 + k];
    __syncthreads();
    const float* wrow = Wg + (size_t)l * DD * HD + (size_t)k * HD + h * 128;
    float accs = 0.f, accd = 0.f;
    for (int d = 0; d < 128; d++) {
        float w = wrow[d];
        accs += w * sa[d];
        accd += w * sd[d];
    }
    g_wsd[(l * 8 + h) * 128 + k]     = accs;
    g_wsd[(l * 8 + h + 4) * 128 + k] = accd;
}

// ---------------- dots from xh directly ----------------
__global__ __launch_bounds__(128) void k_dots2(const float* __restrict__ wsd) {
    __shared__ float sws[8][128];
    int t = threadIdx.x;
    ((float4*)sws)[t]       = ((const float4*)wsd)[t];
    ((float4*)sws)[t + 128] = ((const float4*)wsd)[t + 128];
    __syncthreads();
    int warp = t >> 5, lane = t & 31;
    int n = blockIdx.x * 4 + warp;
    if (n >= NV) return;
    uint2 raw = *(const uint2*)(g_xh + (size_t)n * DD + lane * 4);
    float2 fa = __half22float2(*(__half2*)&raw.x);
    float2 fb = __half22float2(*(__half2*)&raw.y);
    float acc[8];
#pragma unroll
    for (int h = 0; h < 8; h++) {
        float4 wv = *(const float4*)&sws[h][lane * 4];
        acc[h] = fa.x * wv.x + fa.y * wv.y + fb.x * wv.z + fb.y * wv.w;
    }
#pragma unroll
    for (int h = 0; h < 8; h++)
#pragma unroll
        for (int o = 16; o; o >>= 1)
            acc[h] += __shfl_xor_sync(0xffffffffu, acc[h], o);
    if (lane == 0) {
        g_as[n * 4 + 0] = acc[0]; g_as[n * 4 + 1] = acc[1];
        g_as[n * 4 + 2] = acc[2]; g_as[n * 4 + 3] = acc[3];
        g_ad[n * 4 + 0] = acc[4]; g_ad[n * 4 + 1] = acc[5];
        g_ad[n * 4 + 2] = acc[6]; g_ad[n * 4 + 3] = acc[7];
    }
}

// ---------------- CSR build ----------------
__global__ void k_count(const void* ei) {
    int e = (blockIdx.x * 256 + threadIdx.x) * 2;
    if (e < EE) {
        int d0, d1;
        if (g_is64) {
            longlong2 v = ((const longlong2*)ei)[(EE + e) >> 1];
            d0 = (int)v.x; d1 = (int)v.y;
        } else {
            int2 v = ((const int2*)ei)[(EE + e) >> 1];
            d0 = v.x; d1 = v.y;
        }
        atomicAdd(&g_deg[d0], 1);
        atomicAdd(&g_deg[d1], 1);
    }
}

__global__ __launch_bounds__(1024) void k_scan() {
    const int PER = 20;
    __shared__ int wsum[32];
    int t = threadIdx.x, lane = t & 31, w = t >> 5;
    int v[PER];
    int base = t * PER;
    int run = 0;
    if (base < NV) {
        const int4* p = (const int4*)(g_deg + base);
#pragma unroll
        for (int q = 0; q < 5; q++) {
            int4 d = p[q];
            run += d.x; v[q * 4 + 0] = run;
            run += d.y; v[q * 4 + 1] = run;
            run += d.z; v[q * 4 + 2] = run;
            run += d.w; v[q * 4 + 3] = run;
        }
    } else {
#pragma unroll
        for (int q = 0; q < PER; q++) v[q] = 0;
    }
    int tot = run, sc = tot;
#pragma unroll
    for (int o = 1; o < 32; o <<= 1) {
        int u = __shfl_up_sync(0xffffffffu, sc, o);
        if (lane >= o) sc += u;
    }
    if (lane == 31) wsum[w] = sc;
    __syncthreads();
    if (w == 0) {
        int s = wsum[lane];
#pragma unroll
        for (int o = 1; o < 32; o <<= 1) {
            int u = __shfl_up_sync(0xffffffffu, s, o);
            if (lane >= o) s += u;
        }
        wsum[lane] = s;
    }
    __syncthreads();
    int throff = ((w > 0) ? wsum[w - 1] : 0) + sc - tot;
    if (t == 0) g_rowptr[0] = 0;
    if (base < NV) {
#pragma unroll
        for (int q = 0; q < PER; q++) {
            int idx = base + q;
            int startq = throff + (q > 0 ? v[q - 1] : 0);
            g_rowptr[idx + 1] = throff + v[q];
            g_col[startq] = idx;        // self loop at slot 0
            g_cursor[idx] = startq + 1;
        }
    }
}
__global__ void k_scatter(const void* ei) {
    int e = (blockIdx.x * 256 + threadIdx.x) * 2;
    if (e < EE) {
        int s0, s1, d0, d1;
        if (g_is64) {
            longlong2 sv = ((const longlong2*)ei)[e >> 1];
            longlong2 dv = ((const longlong2*)ei)[(EE + e) >> 1];
            s0 = (int)sv.x; s1 = (int)sv.y; d0 = (int)dv.x; d1 = (int)dv.y;
        } else {
            int2 sv = ((const int2*)ei)[e >> 1];
            int2 dv = ((const int2*)ei)[(EE + e) >> 1];
            s0 = sv.x; s1 = sv.y; d0 = dv.x; d1 = dv.y;
        }
        g_col[atomicAdd(&g_cursor[d0], 1)] = s0;
        g_col[atomicAdd(&g_cursor[d1], 1)] = s1;
    }
}

// ---------------- fp16 tensor-core GEMM: block tile 128x64, warp tile 32x32 ----------------
#define GSMEM 53248

__global__ __launch_bounds__(256, 3) void gemm_h(
    const __half* __restrict__ A, const __half* __restrict__ B,
    __half* __restrict__ Ch, int Ncols)
{
    extern __shared__ char dsm[];
    __half* As = (__half*)dsm;
    __half* Bs = As + 128 * 136;
    float*  stage = (float*)dsm;

    int bm = blockIdx.y * 128, bn = blockIdx.x * 64;
    int t = threadIdx.x, warp = t >> 5, lane = t & 31;
    int wr = warp & 3, wc = warp >> 2;

    wmma::fragment<wmma::accumulator, 16, 16, 16, float> acc[2][2];
#pragma unroll
    for (int fr = 0; fr < 2; fr++)
#pragma unroll
        for (int fc = 0; fc < 2; fc++)
            wmma::fill_fragment(acc[fr][fc], 0.f);

#pragma unroll
    for (int i = 0; i < 8; i++) {
        int idx = t + i * 256;
        int r = idx >> 4, c8 = (idx & 15) * 8;
        *(uint4*)(As + r * 136 + c8) = *(const uint4*)(A + (size_t)(bm + r) * 128 + c8);
    }
#pragma unroll
    for (int i = 0; i < 4; i++) {
        int idx = t + i * 256;
        int r = idx >> 3, c8 = (idx & 7) * 8;
        *(uint4*)(Bs + r * 72 + c8) = *(const uint4*)(B + (size_t)r * Ncols + bn + c8);
    }
    __syncthreads();

#pragma unroll
    for (int k = 0; k < 8; k++) {
        wmma::fragment<wmma::matrix_a, 16, 16, 16, __half, wmma::row_major> af[2];
        wmma::fragment<wmma::matrix_b, 16, 16, 16, __half, wmma::row_major> bf[2];
#pragma unroll
        for (int fr = 0; fr < 2; fr++)
            wmma::load_matrix_sync(af[fr], &As[(wr * 32 + fr * 16) * 136 + k * 16], 136);
#pragma unroll
        for (int fc = 0; fc < 2; fc++)
            wmma::load_matrix_sync(bf[fc], &Bs[(k * 16) * 72 + wc * 32 + fc * 16], 72);
#pragma unroll
        for (int fr = 0; fr < 2; fr++)
#pragma unroll
            for (int fc = 0; fc < 2; fc++)
                wmma::mma_sync(acc[fr][fc], af[fr], bf[fc], acc[fr][fc]);
    }
    __syncthreads();

    float* ws = stage + warp * 1152;
#pragma unroll
    for (int fr = 0; fr < 2; fr++)
#pragma unroll
        for (int fc = 0; fc < 2; fc++)
            wmma::store_matrix_sync(&ws[fr * 16 * 36 + fc * 16], acc[fr][fc], 36,
                                    wmma::mem_row_major);
    __syncwarp();
    for (int i = lane; i < 32 * 8; i += 32) {
        int r = i >> 3, c4 = (i & 7) * 4;
        __half2 h0 = __floats2half2_rn(ws[r * 36 + c4], ws[r * 36 + c4 + 1]);
        __half2 h1 = __floats2half2_rn(ws[r * 36 + c4 + 2], ws[r * 36 + c4 + 3]);
        uint2 packed;
        packed.x = *(unsigned*)&h0;
        packed.y = *(unsigned*)&h1;
        *(uint2*)(Ch + (size_t)(bm + wr * 32 + r) * Ncols + bn + wc * 32 + c4) = packed;
    }
}

// ---------------- fused FFN, M-tile = 64 ----------------
#define FM 64
#define FTILES (NV2 / FM)
#define FSMEM 69632

__global__ __launch_bounds__(256) void k_ffn(
    const __half* __restrict__ W1, const __half* __restrict__ W2,
    const float* __restrict__ b1, const float* __restrict__ b2,
    const float* __restrict__ nw, float* __restrict__ outF)
{
    extern __shared__ char dsm[];
    __half* As = (__half*)dsm;
    __half* Ws = As + FM * 136;
    float*  stage = (float*)dsm;
    __half* Hs = (__half*)(dsm + 52224);
    float*  Brep = (float*)(dsm + 52224);

    int bm = blockIdx.x * FM;
    int t = threadIdx.x, warp = t >> 5, lane = t & 31;
    int wc = warp;

    for (int i = t; i < 16 * 128; i += 256) {
        int r = i >> 7, c = i & 127;
        Brep[r * 136 + c] = b1[c];
    }
#pragma unroll
    for (int i = 0; i < 4; i++) {
        int idx = t + i * 256;
        int r = idx >> 4, c8 = (idx & 15) * 8;
        *(uint4*)(As + r * 136 + c8) = *(const uint4*)(g_xh + (size_t)(bm + r) * 128 + c8);
    }
#pragma unroll
    for (int i = 0; i < 8; i++) {
        int idx = t + i * 256;
        int r = idx >> 4, c8 = (idx & 15) * 8;
        *(uint4*)(Ws + r * 136 + c8) = *(const uint4*)(W1 + (size_t)r * 128 + c8);
    }
    __syncthreads();

    wmma::fragment<wmma::accumulator, 16, 16, 16, float> acc[4];
#pragma unroll
    for (int fr = 0; fr < 4; fr++)
        wmma::load_matrix_sync(acc[fr], &Brep[wc * 16], 136, wmma::mem_row_major);

#pragma unroll
    for (int k = 0; k < 8; k++) {
        wmma::fragment<wmma::matrix_a, 16, 16, 16, __half, wmma::row_major> af[4];
        wmma::fragment<wmma::matrix_b, 16, 16, 16, __half, wmma::row_major> bf;
#pragma unroll
        for (int fr = 0; fr < 4; fr++)
            wmma::load_matrix_sync(af[fr], &As[(fr * 16) * 136 + k * 16], 136);
        wmma::load_matrix_sync(bf, &Ws[(k * 16) * 136 + wc * 16], 136);
#pragma unroll
        for (int fr = 0; fr < 4; fr++)
            wmma::mma_sync(acc[fr], af[fr], bf, acc[fr]);
    }
    __syncthreads();

#pragma unroll
    for (int fr = 0; fr < 4; fr++) {
#pragma unroll
        for (int i = 0; i < acc[fr].num_elements; i++)
            acc[fr].x[i] = fmaxf(acc[fr].x[i], 0.f);
        wmma::store_matrix_sync(&stage[(fr * 16) * 132 + wc * 16], acc[fr], 132,
                                wmma::mem_row_major);
    }
    __syncthreads();

    for (int i = t; i < FM * 32; i += 256) {
        int r = i >> 5, c4 = (i & 31) * 4;
        float4 v = *(const float4*)&stage[r * 132 + c4];
        __half2 h0 = __floats2half2_rn(v.x, v.y);
        __half2 h1 = __floats2half2_rn(v.z, v.w);
        uint2 packed;
        packed.x = *(unsigned*)&h0;
        packed.y = *(unsigned*)&h1;
        *(uint2*)(Hs + r * 136 + c4) = packed;
    }
    __syncthreads();

#pragma unroll
    for (int i = 0; i < 8; i++) {
        int idx = t + i * 256;
        int r = idx >> 4, c8 = (idx & 15) * 8;
        *(uint4*)(Ws + r * 136 + c8) = *(const uint4*)(W2 + (size_t)r * 128 + c8);
    }
    __syncthreads();

#pragma unroll
    for (int fr = 0; fr < 4; fr++)
        wmma::fill_fragment(acc[fr], 0.f);

#pragma unroll
    for (int k = 0; k < 8; k++) {
        wmma::fragment<wmma::matrix_a, 16, 16, 16, __half, wmma::row_major> af[4];
        wmma::fragment<wmma::matrix_b, 16, 16, 16, __half, wmma::row_major> bf;
#pragma unroll
        for (int fr = 0; fr < 4; fr++)
            wmma::load_matrix_sync(af[fr], &Hs[(fr * 16) * 136 + k * 16], 136);
        wmma::load_matrix_sync(bf, &Ws[(k * 16) * 136 + wc * 16], 136);
#pragma unroll
        for (int fr = 0; fr < 4; fr++)
            wmma::mma_sync(acc[fr], af[fr], bf, acc[fr]);
    }
    __syncthreads();

#pragma unroll
    for (int fr = 0; fr < 4; fr++)
        wmma::store_matrix_sync(&stage[(fr * 16) * 132 + wc * 16], acc[fr], 132,
                                wmma::mem_row_major);
    __syncthreads();

    float4 nwv = *(const float4*)&nw[lane * 4];
    float4 b2v = *(const float4*)&b2[lane * 4];
    for (int r = warp; r < FM; r += 8) {
        size_t row = (size_t)(bm + r);
        float4 xr = *(const float4*)&g_x[row * 128 + lane * 4];
        float4 st = *(const float4*)&stage[r * 132 + lane * 4];
        float v0 = xr.x + st.x + b2v.x, v1 = xr.y + st.y + b2v.y;
        float v2 = xr.z + st.z + b2v.z, v3 = xr.w + st.w + b2v.w;
        float ss = v0 * v0 + v1 * v1 + v2 * v2 + v3 * v3;
#pragma unroll
        for (int o = 16; o; o >>= 1) ss += __shfl_xor_sync(0xffffffffu, ss, o);
        float rr = rsqrtf(ss * (1.0f / DD) + EPS_);
        float o0 = v0 * rr * nwv.x, o1 = v1 * rr * nwv.y;
        float o2 = v2 * rr * nwv.z, o3 = v3 * rr * nwv.w;
        if (outF) {
            if (row < NV)
                *(float4*)&outF[row * 128 + lane * 4] = make_float4(o0, o1, o2, o3);
        } else {
            *(float4*)&g_x[row * 128 + lane * 4] = make_float4(o0, o1, o2, o3);
            __half2 h0 = __floats2half2_rn(o0, o1);
            __half2 h1 = __floats2half2_rn(o2, o3);
            uint2 packed;
            packed.x = *(unsigned*)&h0;
            packed.y = *(unsigned*)&h1;
            *(uint2*)&g_xh[row * 128 + lane * 4] = packed;
        }
    }
}

__device__ __forceinline__ float lrelu(float x) { return x > 0.f ? x : 0.2f * x; }

__device__ __forceinline__ void comb(float& m, float& s, float m2, float s2) {
    float M = fmaxf(m, m2);
    s = s * __expf(m - M) + s2 * __expf(m2 - M);
    m = M;
}

// ---------------- fused GAT aggregation: warp-per-head (R9 form) ----------------
__global__ __launch_bounds__(128) void k_agg(const float* __restrict__ bias,
                                             const float* __restrict__ nw) {
    int n = blockIdx.x, t = threadIdx.x;
    int w = t >> 5, lane = t & 31;
    int start = g_rowptr[n];
    int deg = g_rowptr[n + 1] - start;

    __shared__ float xatt[4][128];
    __shared__ float sred[4];

    float adv = g_ad[n * 4 + w];

    float m = -1e30f, s = 0.f;
    int src0 = 0; float e0 = -1e30f;
    for (int j = lane; j < deg; j += 32) {
        int src = g_col[start + j];
        float e = lrelu(g_as[src * 4 + w] + adv);
        if (j < 32) { src0 = src; e0 = e; }
        comb(m, s, e, 1.f);
    }
#pragma unroll
    for (int o = 16; o; o >>= 1) {
        float m2 = __shfl_xor_sync(0xffffffffu, m, o);
        float s2 = __shfl_xor_sync(0xffffffffu, s, o);
        comb(m, s, m2, s2);
    }
    float M = m;
    float inv = 1.f / s;

    float4 acc = make_float4(0.f, 0.f, 0.f, 0.f);
    for (int c0 = 0; c0 < deg; c0 += 32) {
        int j = c0 + lane;
        int src; float al;
        if (c0 == 0) {
            src = src0;
            al = (lane < deg) ? __expf(e0 - M) * inv : 0.f;
        } else {
            src = 0; al = 0.f;
            if (j < deg) {
                src = g_col[start + j];
                al = __expf(lrelu(g_as[src * 4 + w] + adv) - M) * inv;
            }
        }
        int cnt = min(32, deg - c0);
        for (int jj = 0; jj < cnt; jj++) {
            float a = __shfl_sync(0xffffffffu, al, jj);
            int sj = __shfl_sync(0xffffffffu, src, jj);
            uint2 raw = *(const uint2*)(g_xph + (size_t)sj * HD + w * 128 + lane * 4);
            float2 f0 = __half22float2(*(__half2*)&raw.x);
            float2 f1 = __half22float2(*(__half2*)&raw.y);
            acc.x += a * f0.x;
            acc.y += a * f0.y;
            acc.z += a * f1.x;
            acc.w += a * f1.y;
        }
    }
    *(float4*)&xatt[w][lane * 4] = acc;
    __syncthreads();

    float a = 0.25f * (xatt[0][t] + xatt[1][t] + xatt[2][t] + xatt[3][t]);
    float v = g_x[n * DD + t] + a + bias[t];
    float ss = v * v;
#pragma unroll
    for (int o = 16; o; o >>= 1) ss += __shfl_xor_sync(0xffffffffu, ss, o);
    if (lane == 0) sred[w] = ss;
    __syncthreads();
    float tot = sred[0] + sred[1] + sred[2] + sred[3];
    float r = rsqrtf(tot * (1.0f / DD) + EPS_);
    float o = v * r * nw[t];
    g_x[n * DD + t] = o;
    g_xh[n * DD + t] = __float2half(o);
}

// ---------------- host ----------------
extern "C" void kernel_launch(void* const* d_in, const int* in_sizes, int n_in,
                              void* d_out, int out_size) {
    const float* x        = (const float*)d_in[0];
    const float* W_gat    = (const float*)d_in[1];
    const float* att_src  = (const float*)d_in[2];
    const float* att_dst  = (const float*)d_in[3];
    const float* bias_gat = (const float*)d_in[4];
    const float* W1       = (const float*)d_in[5];
    const float* b1       = (const float*)d_in[6];
    const float* W2       = (const float*)d_in[7];
    const float* b2       = (const float*)d_in[8];
    const float* n1w      = (const float*)d_in[9];
    const float* n2w      = (const float*)d_in[10];
    const void*  ei       = d_in[11];

    static cudaStream_t s2 = nullptr;
    static cudaEvent_t evA = nullptr, evB = nullptr;
    if (!s2) {
        cudaFuncSetAttribute(gemm_h, cudaFuncAttributeMaxDynamicSharedMemorySize, GSMEM);
        cudaFuncSetAttribute(k_ffn, cudaFuncAttributeMaxDynamicSharedMemorySize, FSMEM);
        cudaStreamCreate(&s2);
        cudaEventCreateWithFlags(&evA, cudaEventDisableTiming);
        cudaEventCreateWithFlags(&evB, cudaEventDisableTiming);
    }

    __half *xh, *xph, *Wg, *W1h, *W2h;
    float* wsd;
    cudaGetSymbolAddress((void**)&xh,  g_xh);
    cudaGetSymbolAddress((void**)&xph, g_xph);
    cudaGetSymbolAddress((void**)&Wg,  g_Wg);
    cudaGetSymbolAddress((void**)&W1h, g_W1h);
    cudaGetSymbolAddress((void**)&W2h, g_W2h);
    cudaGetSymbolAddress((void**)&wsd, g_wsd);

    // main stream: setup -> gemm0(4th submitted) -> dots -> agg -> ffn -> ...
    // side stream s2: CSR build + att-fold, single fork/join (R9 pattern).
    k_setup<<<2500, 256>>>((const float4*)x, W_gat, W1, W2, (const unsigned*)ei);
    cudaEventRecord(evA);
    cudaStreamWaitEvent(s2, evA, 0);
    k_count<<<(EE / 2 + 255) / 256, 256, 0, s2>>>(ei);
    k_scan<<<1, 1024, 0, s2>>>();
    gemm_h<<<dim3(HD / 64, MTILES), 256, GSMEM>>>(xh, Wg, xph, HD);   // 4th launch
    k_scatter<<<(EE / 2 + 255) / 256, 256, 0, s2>>>(ei);
    k_prep<<<4 * LL, 128, 0, s2>>>(W_gat, att_src, att_dst);
    cudaEventRecord(evB, s2);
    cudaStreamWaitEvent(0, evB, 0);

    for (int i = 0; i < LL; i++) {
        if (i > 0) {
            gemm_h<<<dim3(HD / 64, MTILES), 256, GSMEM>>>(
                xh, Wg + (size_t)i * DD * HD, xph, HD);
        }
        k_dots2<<<(NV + 3) / 4, 128>>>(wsd + i * 8 * DD);
        k_agg<<<NV, 128>>>(bias_gat + i * DD, n1w + i * DD);
        k_ffn<<<FTILES, 256, FSMEM>>>(
            W1h + (size_t)i * DD * DD, W2h + (size_t)i * DD * DD,
            b1 + i * DD, b2 + i * DD, n2w + i * DD,
            (i == LL - 1) ? (float*)d_out : nullptr);
    }
}

// round 16
// speedup vs baseline: 1.1121x; 1.1121x over previous
#include <cuda_runtime.h>
#include <cuda_fp16.h>
#include <mma.h>
using namespace nvcuda;

#define NV 20000
#define EE 320000
#define DD 128
#define HD 512
#define LL 3
#define MTILES 157
#define NV2 (MTILES * 128)
#define EPS_ 1.1920929e-07f

// ---------------- static device scratch ----------------
__device__ float  g_x  [NV2 * DD];
__device__ __half g_xh [NV2 * DD];
__device__ __half g_xph[(size_t)NV2 * HD];
__device__ __half g_Wg [LL * DD * HD];
__device__ __half g_W1h[LL * DD * DD];
__device__ __half g_W2h[LL * DD * DD];
__device__ float  g_wsd[LL * 8 * DD];     // folded att weights [L][8][128] (h<4: src, h>=4: dst)
__device__ float  g_as[NV * 4];
__device__ float  g_ad[NV * 4];
__device__ int    g_rowptr[NV + 1];
__device__ int    g_deg[NV];
__device__ int    g_cursor[NV];
__device__ int    g_col[EE + NV];
__device__ int    g_is64;

// ---------------- fused setup ----------------
#define WHALF ((LL * DD * HD + 2 * LL * DD * DD) / 2)

__global__ void k_setup(const float4* __restrict__ x,
                        const float* __restrict__ Wg,
                        const float* __restrict__ W1,
                        const float* __restrict__ W2,
                        const unsigned* __restrict__ ei_w) {
    int i = blockIdx.x * 256 + threadIdx.x;
    if (i < NV * DD / 4) {
        float4 v = x[i];
        ((float4*)g_x)[i] = v;
        ((__half2*)g_xh)[i * 2]     = __floats2half2_rn(v.x, v.y);
        ((__half2*)g_xh)[i * 2 + 1] = __floats2half2_rn(v.z, v.w);
    }
    if (i < WHALF) {
        int j = i * 2;
        const float* src; __half* dst; int off;
        if (j < LL * DD * HD)                     { src = Wg; dst = g_Wg;  off = j; }
        else if (j < LL * DD * HD + LL * DD * DD) { src = W1; dst = g_W1h; off = j - LL * DD * HD; }
        else                                      { src = W2; dst = g_W2h; off = j - LL * DD * HD - LL * DD * DD; }
        float2 v = *(const float2*)(src + off);
        *(__half2*)(dst + off) = __floats2half2_rn(v.x, v.y);
    }
    if (i < NV) g_deg[i] = 1;
    if (blockIdx.x == 0) {
        __shared__ unsigned acc;
        if (threadIdx.x == 0) acc = 0u;
        __syncthreads();
        unsigned v = 0;
        for (int k = threadIdx.x; k < 2048; k += 256) v |= ei_w[2 * k + 1];
        if (v) atomicOr(&acc, 1u);
        __syncthreads();
        if (threadIdx.x == 0) g_is64 = (acc == 0u) ? 1 : 0;
    }
}

// ---------------- fold att vectors through W_gat (coalesced: warp per k-row) ----------------
__global__ __launch_bounds__(128) void k_prep(const float* __restrict__ Wg,
                                              const float* __restrict__ att_s,
                                              const float* __restrict__ att_d) {
    int l = blockIdx.x >> 2, h = blockIdx.x & 3;
    int t = threadIdx.x, w = t >> 5, lane = t & 31;
    __shared__ float sa[128], sd[128];
    sa[t] = att_s[(l * 4 + h) * 128 + t];
    sd[t] = att_d[(l * 4 + h) * 128 + t];
    __syncthreads();
    float4 av = *(const float4*)&sa[lane * 4];
    float4 dv = *(const float4*)&sd[lane * 4];
    for (int k = w; k < 128; k += 4) {
        const float* wrow = Wg + (size_t)l * DD * HD + (size_t)k * HD + h * 128;
        float4 wv = *(const float4*)&wrow[lane * 4];   // coalesced 128B per warp
        float ps = wv.x * av.x + wv.y * av.y + wv.z * av.z + wv.w * av.w;
        float pd = wv.x * dv.x + wv.y * dv.y + wv.z * dv.z + wv.w * dv.w;
#pragma unroll
        for (int o = 16; o; o >>= 1) {
            ps += __shfl_xor_sync(0xffffffffu, ps, o);
            pd += __shfl_xor_sync(0xffffffffu, pd, o);
        }
        if (lane == 0) {
            g_wsd[(l * 8 + h) * 128 + k]     = ps;
            g_wsd[(l * 8 + h + 4) * 128 + k] = pd;
        }
    }
}

// ---------------- dots from xh directly ----------------
__global__ __launch_bounds__(128) void k_dots2(const float* __restrict__ wsd) {
    __shared__ float sws[8][128];
    int t = threadIdx.x;
    ((float4*)sws)[t]       = ((const float4*)wsd)[t];
    ((float4*)sws)[t + 128] = ((const float4*)wsd)[t + 128];
    __syncthreads();
    int warp = t >> 5, lane = t & 31;
    int n = blockIdx.x * 4 + warp;
    if (n >= NV) return;
    uint2 raw = *(const uint2*)(g_xh + (size_t)n * DD + lane * 4);
    float2 fa = __half22float2(*(__half2*)&raw.x);
    float2 fb = __half22float2(*(__half2*)&raw.y);
    float acc[8];
#pragma unroll
    for (int h = 0; h < 8; h++) {
        float4 wv = *(const float4*)&sws[h][lane * 4];
        acc[h] = fa.x * wv.x + fa.y * wv.y + fb.x * wv.z + fb.y * wv.w;
    }
#pragma unroll
    for (int h = 0; h < 8; h++)
#pragma unroll
        for (int o = 16; o; o >>= 1)
            acc[h] += __shfl_xor_sync(0xffffffffu, acc[h], o);
    if (lane == 0) {
        g_as[n * 4 + 0] = acc[0]; g_as[n * 4 + 1] = acc[1];
        g_as[n * 4 + 2] = acc[2]; g_as[n * 4 + 3] = acc[3];
        g_ad[n * 4 + 0] = acc[4]; g_ad[n * 4 + 1] = acc[5];
        g_ad[n * 4 + 2] = acc[6]; g_ad[n * 4 + 3] = acc[7];
    }
}

// ---------------- CSR build ----------------
__global__ void k_count(const void* ei) {
    int e = (blockIdx.x * 256 + threadIdx.x) * 2;
    if (e < EE) {
        int d0, d1;
        if (g_is64) {
            longlong2 v = ((const longlong2*)ei)[(EE + e) >> 1];
            d0 = (int)v.x; d1 = (int)v.y;
        } else {
            int2 v = ((const int2*)ei)[(EE + e) >> 1];
            d0 = v.x; d1 = v.y;
        }
        atomicAdd(&g_deg[d0], 1);
        atomicAdd(&g_deg[d1], 1);
    }
}

__global__ __launch_bounds__(1024) void k_scan() {
    const int PER = 20;
    __shared__ int wsum[32];
    int t = threadIdx.x, lane = t & 31, w = t >> 5;
    int v[PER];
    int base = t * PER;
    int run = 0;
    if (base < NV) {
        const int4* p = (const int4*)(g_deg + base);
#pragma unroll
        for (int q = 0; q < 5; q++) {
            int4 d = p[q];
            run += d.x; v[q * 4 + 0] = run;
            run += d.y; v[q * 4 + 1] = run;
            run += d.z; v[q * 4 + 2] = run;
            run += d.w; v[q * 4 + 3] = run;
        }
    } else {
#pragma unroll
        for (int q = 0; q < PER; q++) v[q] = 0;
    }
    int tot = run, sc = tot;
#pragma unroll
    for (int o = 1; o < 32; o <<= 1) {
        int u = __shfl_up_sync(0xffffffffu, sc, o);
        if (lane >= o) sc += u;
    }
    if (lane == 31) wsum[w] = sc;
    __syncthreads();
    if (w == 0) {
        int s = wsum[lane];
#pragma unroll
        for (int o = 1; o < 32; o <<= 1) {
            int u = __shfl_up_sync(0xffffffffu, s, o);
            if (lane >= o) s += u;
        }
        wsum[lane] = s;
    }
    __syncthreads();
    int throff = ((w > 0) ? wsum[w - 1] : 0) + sc - tot;
    if (t == 0) g_rowptr[0] = 0;
    if (base < NV) {
#pragma unroll
        for (int q = 0; q < PER; q++) {
            int idx = base + q;
            int startq = throff + (q > 0 ? v[q - 1] : 0);
            g_rowptr[idx + 1] = throff + v[q];
            g_col[startq] = idx;        // self loop at slot 0
            g_cursor[idx] = startq + 1;
        }
    }
}
__global__ void k_scatter(const void* ei) {
    int e = (blockIdx.x * 256 + threadIdx.x) * 2;
    if (e < EE) {
        int s0, s1, d0, d1;
        if (g_is64) {
            longlong2 sv = ((const longlong2*)ei)[e >> 1];
            longlong2 dv = ((const longlong2*)ei)[(EE + e) >> 1];
            s0 = (int)sv.x; s1 = (int)sv.y; d0 = (int)dv.x; d1 = (int)dv.y;
        } else {
            int2 sv = ((const int2*)ei)[e >> 1];
            int2 dv = ((const int2*)ei)[(EE + e) >> 1];
            s0 = sv.x; s1 = sv.y; d0 = dv.x; d1 = dv.y;
        }
        g_col[atomicAdd(&g_cursor[d0], 1)] = s0;
        g_col[atomicAdd(&g_cursor[d1], 1)] = s1;
    }
}

// ---------------- fp16 tensor-core GEMM: block tile 128x64, warp tile 32x32 ----------------
#define GSMEM 53248

__global__ __launch_bounds__(256, 3) void gemm_h(
    const __half* __restrict__ A, const __half* __restrict__ B,
    __half* __restrict__ Ch, int Ncols)
{
    extern __shared__ char dsm[];
    __half* As = (__half*)dsm;
    __half* Bs = As + 128 * 136;
    float*  stage = (float*)dsm;

    int bm = blockIdx.y * 128, bn = blockIdx.x * 64;
    int t = threadIdx.x, warp = t >> 5, lane = t & 31;
    int wr = warp & 3, wc = warp >> 2;

    wmma::fragment<wmma::accumulator, 16, 16, 16, float> acc[2][2];
#pragma unroll
    for (int fr = 0; fr < 2; fr++)
#pragma unroll
        for (int fc = 0; fc < 2; fc++)
            wmma::fill_fragment(acc[fr][fc], 0.f);

#pragma unroll
    for (int i = 0; i < 8; i++) {
        int idx = t + i * 256;
        int r = idx >> 4, c8 = (idx & 15) * 8;
        *(uint4*)(As + r * 136 + c8) = *(const uint4*)(A + (size_t)(bm + r) * 128 + c8);
    }
#pragma unroll
    for (int i = 0; i < 4; i++) {
        int idx = t + i * 256;
        int r = idx >> 3, c8 = (idx & 7) * 8;
        *(uint4*)(Bs + r * 72 + c8) = *(const uint4*)(B + (size_t)r * Ncols + bn + c8);
    }
    __syncthreads();

#pragma unroll
    for (int k = 0; k < 8; k++) {
        wmma::fragment<wmma::matrix_a, 16, 16, 16, __half, wmma::row_major> af[2];
        wmma::fragment<wmma::matrix_b, 16, 16, 16, __half, wmma::row_major> bf[2];
#pragma unroll
        for (int fr = 0; fr < 2; fr++)
            wmma::load_matrix_sync(af[fr], &As[(wr * 32 + fr * 16) * 136 + k * 16], 136);
#pragma unroll
        for (int fc = 0; fc < 2; fc++)
            wmma::load_matrix_sync(bf[fc], &Bs[(k * 16) * 72 + wc * 32 + fc * 16], 72);
#pragma unroll
        for (int fr = 0; fr < 2; fr++)
#pragma unroll
            for (int fc = 0; fc < 2; fc++)
                wmma::mma_sync(acc[fr][fc], af[fr], bf[fc], acc[fr][fc]);
    }
    __syncthreads();

    float* ws = stage + warp * 1152;
#pragma unroll
    for (int fr = 0; fr < 2; fr++)
#pragma unroll
        for (int fc = 0; fc < 2; fc++)
            wmma::store_matrix_sync(&ws[fr * 16 * 36 + fc * 16], acc[fr][fc], 36,
                                    wmma::mem_row_major);
    __syncwarp();
    for (int i = lane; i < 32 * 8; i += 32) {
        int r = i >> 3, c4 = (i & 7) * 4;
        __half2 h0 = __floats2half2_rn(ws[r * 36 + c4], ws[r * 36 + c4 + 1]);
        __half2 h1 = __floats2half2_rn(ws[r * 36 + c4 + 2], ws[r * 36 + c4 + 3]);
        uint2 packed;
        packed.x = *(unsigned*)&h0;
        packed.y = *(unsigned*)&h1;
        *(uint2*)(Ch + (size_t)(bm + wr * 32 + r) * Ncols + bn + wc * 32 + c4) = packed;
    }
}

// ---------------- fused FFN, M-tile = 64 ----------------
#define FM 64
#define FTILES (NV2 / FM)
#define FSMEM 69632

__global__ __launch_bounds__(256) void k_ffn(
    const __half* __restrict__ W1, const __half* __restrict__ W2,
    const float* __restrict__ b1, const float* __restrict__ b2,
    const float* __restrict__ nw, float* __restrict__ outF)
{
    extern __shared__ char dsm[];
    __half* As = (__half*)dsm;
    __half* Ws = As + FM * 136;
    float*  stage = (float*)dsm;
    __half* Hs = (__half*)(dsm + 52224);
    float*  Brep = (float*)(dsm + 52224);

    int bm = blockIdx.x * FM;
    int t = threadIdx.x, warp = t >> 5, lane = t & 31;
    int wc = warp;

    for (int i = t; i < 16 * 128; i += 256) {
        int r = i >> 7, c = i & 127;
        Brep[r * 136 + c] = b1[c];
    }
#pragma unroll
    for (int i = 0; i < 4; i++) {
        int idx = t + i * 256;
        int r = idx >> 4, c8 = (idx & 15) * 8;
        *(uint4*)(As + r * 136 + c8) = *(const uint4*)(g_xh + (size_t)(bm + r) * 128 + c8);
    }
#pragma unroll
    for (int i = 0; i < 8; i++) {
        int idx = t + i * 256;
        int r = idx >> 4, c8 = (idx & 15) * 8;
        *(uint4*)(Ws + r * 136 + c8) = *(const uint4*)(W1 + (size_t)r * 128 + c8);
    }
    __syncthreads();

    wmma::fragment<wmma::accumulator, 16, 16, 16, float> acc[4];
#pragma unroll
    for (int fr = 0; fr < 4; fr++)
        wmma::load_matrix_sync(acc[fr], &Brep[wc * 16], 136, wmma::mem_row_major);

#pragma unroll
    for (int k = 0; k < 8; k++) {
        wmma::fragment<wmma::matrix_a, 16, 16, 16, __half, wmma::row_major> af[4];
        wmma::fragment<wmma::matrix_b, 16, 16, 16, __half, wmma::row_major> bf;
#pragma unroll
        for (int fr = 0; fr < 4; fr++)
            wmma::load_matrix_sync(af[fr], &As[(fr * 16) * 136 + k * 16], 136);
        wmma::load_matrix_sync(bf, &Ws[(k * 16) * 136 + wc * 16], 136);
#pragma unroll
        for (int fr = 0; fr < 4; fr++)
            wmma::mma_sync(acc[fr], af[fr], bf, acc[fr]);
    }
    __syncthreads();

#pragma unroll
    for (int fr = 0; fr < 4; fr++) {
#pragma unroll
        for (int i = 0; i < acc[fr].num_elements; i++)
            acc[fr].x[i] = fmaxf(acc[fr].x[i], 0.f);
        wmma::store_matrix_sync(&stage[(fr * 16) * 132 + wc * 16], acc[fr], 132,
                                wmma::mem_row_major);
    }
    __syncthreads();

    for (int i = t; i < FM * 32; i += 256) {
        int r = i >> 5, c4 = (i & 31) * 4;
        float4 v = *(const float4*)&stage[r * 132 + c4];
        __half2 h0 = __floats2half2_rn(v.x, v.y);
        __half2 h1 = __floats2half2_rn(v.z, v.w);
        uint2 packed;
        packed.x = *(unsigned*)&h0;
        packed.y = *(unsigned*)&h1;
        *(uint2*)(Hs + r * 136 + c4) = packed;
    }
    __syncthreads();

#pragma unroll
    for (int i = 0; i < 8; i++) {
        int idx = t + i * 256;
        int r = idx >> 4, c8 = (idx & 15) * 8;
        *(uint4*)(Ws + r * 136 + c8) = *(const uint4*)(W2 + (size_t)r * 128 + c8);
    }
    __syncthreads();

#pragma unroll
    for (int fr = 0; fr < 4; fr++)
        wmma::fill_fragment(acc[fr], 0.f);

#pragma unroll
    for (int k = 0; k < 8; k++) {
        wmma::fragment<wmma::matrix_a, 16, 16, 16, __half, wmma::row_major> af[4];
        wmma::fragment<wmma::matrix_b, 16, 16, 16, __half, wmma::row_major> bf;
#pragma unroll
        for (int fr = 0; fr < 4; fr++)
            wmma::load_matrix_sync(af[fr], &Hs[(fr * 16) * 136 + k * 16], 136);
        wmma::load_matrix_sync(bf, &Ws[(k * 16) * 136 + wc * 16], 136);
#pragma unroll
        for (int fr = 0; fr < 4; fr++)
            wmma::mma_sync(acc[fr], af[fr], bf, acc[fr]);
    }
    __syncthreads();

#pragma unroll
    for (int fr = 0; fr < 4; fr++)
        wmma::store_matrix_sync(&stage[(fr * 16) * 132 + wc * 16], acc[fr], 132,
                                wmma::mem_row_major);
    __syncthreads();

    float4 nwv = *(const float4*)&nw[lane * 4];
    float4 b2v = *(const float4*)&b2[lane * 4];
    for (int r = warp; r < FM; r += 8) {
        size_t row = (size_t)(bm + r);
        float4 xr = *(const float4*)&g_x[row * 128 + lane * 4];
        float4 st = *(const float4*)&stage[r * 132 + lane * 4];
        float v0 = xr.x + st.x + b2v.x, v1 = xr.y + st.y + b2v.y;
        float v2 = xr.z + st.z + b2v.z, v3 = xr.w + st.w + b2v.w;
        float ss = v0 * v0 + v1 * v1 + v2 * v2 + v3 * v3;
#pragma unroll
        for (int o = 16; o; o >>= 1) ss += __shfl_xor_sync(0xffffffffu, ss, o);
        float rr = rsqrtf(ss * (1.0f / DD) + EPS_);
        float o0 = v0 * rr * nwv.x, o1 = v1 * rr * nwv.y;
        float o2 = v2 * rr * nwv.z, o3 = v3 * rr * nwv.w;
        if (outF) {
            if (row < NV)
                *(float4*)&outF[row * 128 + lane * 4] = make_float4(o0, o1, o2, o3);
        } else {
            *(float4*)&g_x[row * 128 + lane * 4] = make_float4(o0, o1, o2, o3);
            __half2 h0 = __floats2half2_rn(o0, o1);
            __half2 h1 = __floats2half2_rn(o2, o3);
            uint2 packed;
            packed.x = *(unsigned*)&h0;
            packed.y = *(unsigned*)&h1;
            *(uint2*)&g_xh[row * 128 + lane * 4] = packed;
        }
    }
}

__device__ __forceinline__ float lrelu(float x) { return x > 0.f ? x : 0.2f * x; }

__device__ __forceinline__ void comb(float& m, float& s, float m2, float s2) {
    float M = fmaxf(m, m2);
    s = s * __expf(m - M) + s2 * __expf(m2 - M);
    m = M;
}

// ---------------- fused GAT aggregation: warp-per-head (R9 form) ----------------
__global__ __launch_bounds__(128) void k_agg(const float* __restrict__ bias,
                                             const float* __restrict__ nw) {
    int n = blockIdx.x, t = threadIdx.x;
    int w = t >> 5, lane = t & 31;
    int start = g_rowptr[n];
    int deg = g_rowptr[n + 1] - start;

    __shared__ float xatt[4][128];
    __shared__ float sred[4];

    float adv = g_ad[n * 4 + w];

    float m = -1e30f, s = 0.f;
    int src0 = 0; float e0 = -1e30f;
    for (int j = lane; j < deg; j += 32) {
        int src = g_col[start + j];
        float e = lrelu(g_as[src * 4 + w] + adv);
        if (j < 32) { src0 = src; e0 = e; }
        comb(m, s, e, 1.f);
    }
#pragma unroll
    for (int o = 16; o; o >>= 1) {
        float m2 = __shfl_xor_sync(0xffffffffu, m, o);
        float s2 = __shfl_xor_sync(0xffffffffu, s, o);
        comb(m, s, m2, s2);
    }
    float M = m;
    float inv = 1.f / s;

    float4 acc = make_float4(0.f, 0.f, 0.f, 0.f);
    for (int c0 = 0; c0 < deg; c0 += 32) {
        int j = c0 + lane;
        int src; float al;
        if (c0 == 0) {
            src = src0;
            al = (lane < deg) ? __expf(e0 - M) * inv : 0.f;
        } else {
            src = 0; al = 0.f;
            if (j < deg) {
                src = g_col[start + j];
                al = __expf(lrelu(g_as[src * 4 + w] + adv) - M) * inv;
            }
        }
        int cnt = min(32, deg - c0);
        for (int jj = 0; jj < cnt; jj++) {
            float a = __shfl_sync(0xffffffffu, al, jj);
            int sj = __shfl_sync(0xffffffffu, src, jj);
            uint2 raw = *(const uint2*)(g_xph + (size_t)sj * HD + w * 128 + lane * 4);
            float2 f0 = __half22float2(*(__half2*)&raw.x);
            float2 f1 = __half22float2(*(__half2*)&raw.y);
            acc.x += a * f0.x;
            acc.y += a * f0.y;
            acc.z += a * f1.x;
            acc.w += a * f1.y;
        }
    }
    *(float4*)&xatt[w][lane * 4] = acc;
    __syncthreads();

    float a = 0.25f * (xatt[0][t] + xatt[1][t] + xatt[2][t] + xatt[3][t]);
    float v = g_x[n * DD + t] + a + bias[t];
    float ss = v * v;
#pragma unroll
    for (int o = 16; o; o >>= 1) ss += __shfl_xor_sync(0xffffffffu, ss, o);
    if (lane == 0) sred[w] = ss;
    __syncthreads();
    float tot = sred[0] + sred[1] + sred[2] + sred[3];
    float r = rsqrtf(tot * (1.0f / DD) + EPS_);
    float o = v * r * nw[t];
    g_x[n * DD + t] = o;
    g_xh[n * DD + t] = __float2half(o);
}

// ---------------- host ----------------
extern "C" void kernel_launch(void* const* d_in, const int* in_sizes, int n_in,
                              void* d_out, int out_size) {
    const float* x        = (const float*)d_in[0];
    const float* W_gat    = (const float*)d_in[1];
    const float* att_src  = (const float*)d_in[2];
    const float* att_dst  = (const float*)d_in[3];
    const float* bias_gat = (const float*)d_in[4];
    const float* W1       = (const float*)d_in[5];
    const float* b1       = (const float*)d_in[6];
    const float* W2       = (const float*)d_in[7];
    const float* b2       = (const float*)d_in[8];
    const float* n1w      = (const float*)d_in[9];
    const float* n2w      = (const float*)d_in[10];
    const void*  ei       = d_in[11];

    static cudaStream_t s2 = nullptr;
    static cudaEvent_t evA = nullptr, evB = nullptr;
    if (!s2) {
        cudaFuncSetAttribute(gemm_h, cudaFuncAttributeMaxDynamicSharedMemorySize, GSMEM);
        cudaFuncSetAttribute(k_ffn, cudaFuncAttributeMaxDynamicSharedMemorySize, FSMEM);
        cudaStreamCreate(&s2);
        cudaEventCreateWithFlags(&evA, cudaEventDisableTiming);
        cudaEventCreateWithFlags(&evB, cudaEventDisableTiming);
    }

    __half *xh, *xph, *Wg, *W1h, *W2h;
    float* wsd;
    cudaGetSymbolAddress((void**)&xh,  g_xh);
    cudaGetSymbolAddress((void**)&xph, g_xph);
    cudaGetSymbolAddress((void**)&Wg,  g_Wg);
    cudaGetSymbolAddress((void**)&W1h, g_W1h);
    cudaGetSymbolAddress((void**)&W2h, g_W2h);
    cudaGetSymbolAddress((void**)&wsd, g_wsd);

    // main: setup -> prep -> gemm0 -> dots2(0) -> (join) agg0 -> ffn0 -> ...
    // s2: count -> scan -> scatter (CSR only; R9-balanced join).
    k_setup<<<2500, 256>>>((const float4*)x, W_gat, W1, W2, (const unsigned*)ei);
    cudaEventRecord(evA);
    cudaStreamWaitEvent(s2, evA, 0);
    k_count<<<(EE / 2 + 255) / 256, 256, 0, s2>>>(ei);
    k_prep<<<4 * LL, 128>>>(W_gat, att_src, att_dst);
    gemm_h<<<dim3(HD / 64, MTILES), 256, GSMEM>>>(xh, Wg, xph, HD);
    k_scan<<<1, 1024, 0, s2>>>();
    k_dots2<<<(NV + 3) / 4, 128>>>(wsd);
    k_scatter<<<(EE / 2 + 255) / 256, 256, 0, s2>>>(ei);
    cudaEventRecord(evB, s2);
    cudaStreamWaitEvent(0, evB, 0);

    for (int i = 0; i < LL; i++) {
        if (i > 0) {
            gemm_h<<<dim3(HD / 64, MTILES), 256, GSMEM>>>(
                xh, Wg + (size_t)i * DD * HD, xph, HD);
            k_dots2<<<(NV + 3) / 4, 128>>>(wsd + i * 8 * DD);
        }
        k_agg<<<NV, 128>>>(bias_gat + i * DD, n1w + i * DD);
        k_ffn<<<FTILES, 256, FSMEM>>>(
            W1h + (size_t)i * DD * DD, W2h + (size_t)i * DD * DD,
            b1 + i * DD, b2 + i * DD, n2w + i * DD,
            (i == LL - 1) ? (float*)d_out : nullptr);
    }
}